// round 1
// baseline (speedup 1.0000x reference)
#include <cuda_runtime.h>
#include <cstdint>

#define H_FEAT 512
#define W_FEAT 512
#define K_ANCH 9
#define N_ANCH (H_FEAT * W_FEAT * K_ANCH)   // 2359296
#define TOP_K 4000
#define IMG_DIM 16384.0f
#define NMS_IOU_T 0.3f
#define N_BINS 131072
#define CAP 4096
#define COL_BLOCKS 63                        // ceil(4000/64)

// ---------------- static device scratch (no allocation allowed) ----------------
__device__ float               g_scores[N_ANCH];          // 9.4 MB
__device__ unsigned int        g_hist[N_BINS];            // 512 KB
__device__ unsigned int        g_count;
__device__ unsigned int        g_cutbin;
__device__ unsigned long long  g_keys[CAP];
__device__ float               g_x1[TOP_K], g_y1[TOP_K], g_x2[TOP_K], g_y2[TOP_K], g_area[TOP_K];
__device__ unsigned long long  g_mask[(size_t)TOP_K * COL_BLOCKS];   // ~2 MB

// ---------------- helpers (forbid FMA contraction / fast-math drift) ----------
__device__ __forceinline__ float softmax_p1(float l0, float l1, float& p0) {
    float m  = fmaxf(l0, l1);
    float e0 = expf(__fsub_rn(l0, m));
    float e1 = expf(__fsub_rn(l1, m));
    float s  = __fadd_rn(e0, e1);
    p0 = __fdiv_rn(e0, s);
    return __fdiv_rn(e1, s);
}

// ---------------- K0: reset state (graph replays must be deterministic) -------
__global__ void zero_kernel() {
    int i = blockIdx.x * blockDim.x + threadIdx.x;
    if (i < N_BINS) g_hist[i] = 0u;
    if (i == 0) g_count = 0u;
}

// ---------------- K1: scores + histogram --------------------------------------
__global__ void score_kernel(const float* __restrict__ obj) {
    int i = blockIdx.x * blockDim.x + threadIdx.x;
    if (i >= N_ANCH) return;
    int y = i / (W_FEAT * K_ANCH);
    int r = i - y * (W_FEAT * K_ANCH);
    int x = r / K_ANCH;
    int k = r - x * K_ANCH;
    const float* p = obj + ((size_t)(y * W_FEAT + x)) * (2 * K_ANCH) + 2 * k;
    float l0 = p[0], l1 = p[1];
    float p0;
    float p1 = softmax_p1(l0, l1, p0);
    g_scores[i] = p1;
    if (p1 > 0.5f) {
        unsigned bits = __float_as_uint(p1);
        unsigned bin = (bits - 0x3F000000u) >> 6;
        if (bin > (N_BINS - 1)) bin = N_BINS - 1;
        atomicAdd(&g_hist[bin], 1u);
    }
}

// ---------------- K2: find cut bin (cumulative-from-top >= TOP_K) -------------
__global__ void cut_kernel() {
    __shared__ unsigned int csum[1024];
    int t = threadIdx.x;
    unsigned s = 0;
    #pragma unroll 4
    for (int b = 0; b < N_BINS / 1024; b++) s += g_hist[t * (N_BINS / 1024) + b];
    csum[t] = s;
    __syncthreads();
    if (t == 0) {
        unsigned running = 0;
        int cg = -1;
        for (int g = 1023; g >= 0; g--) {
            if (running + csum[g] >= (unsigned)TOP_K) { cg = g; break; }
            running += csum[g];
        }
        unsigned cut = 0;
        if (cg >= 0) {
            int base = cg * (N_BINS / 1024);
            for (int b = base + (N_BINS / 1024) - 1; b >= base; b--) {
                running += g_hist[b];
                if (running >= (unsigned)TOP_K) { cut = (unsigned)b; break; }
            }
        }
        g_cutbin = cut;
    }
}

// ---------------- K3: collect candidates above cut ----------------------------
__global__ void collect_kernel() {
    int i = blockIdx.x * blockDim.x + threadIdx.x;
    if (i >= N_ANCH) return;
    float p1 = g_scores[i];
    if (p1 > 0.5f) {
        unsigned bits = __float_as_uint(p1);
        unsigned bin = (bits - 0x3F000000u) >> 6;
        if (bin > (N_BINS - 1)) bin = N_BINS - 1;
        if (bin >= g_cutbin) {
            unsigned pos = atomicAdd(&g_count, 1u);
            if (pos < CAP) {
                g_keys[pos] = ((unsigned long long)bits << 32) |
                              (unsigned long long)(0xFFFFFFFFu - (unsigned)i);
            }
        }
    }
}

// ---------------- K4: one-block bitonic sort (descending), n = 4096 -----------
__global__ void sort_kernel() {
    __shared__ unsigned long long s[CAP];
    unsigned cnt = g_count;
    if (cnt > CAP) cnt = CAP;
    for (int i = threadIdx.x; i < CAP; i += blockDim.x)
        s[i] = (i < (int)cnt) ? g_keys[i] : 0ULL;
    __syncthreads();
    for (int k = 2; k <= CAP; k <<= 1) {
        for (int j = k >> 1; j > 0; j >>= 1) {
            for (int i = threadIdx.x; i < CAP; i += blockDim.x) {
                int ixj = i ^ j;
                if (ixj > i) {
                    unsigned long long a = s[i], b = s[ixj];
                    bool up = ((i & k) == 0);
                    if (up ? (a < b) : (a > b)) { s[i] = b; s[ixj] = a; }
                }
            }
            __syncthreads();
        }
    }
    for (int i = threadIdx.x; i < CAP; i += blockDim.x) g_keys[i] = s[i];
}

// ---------------- K5: decode boxes, write b & o, prep NMS inputs --------------
__global__ void finalize_kernel(const float* __restrict__ obj,
                                const float* __restrict__ reg,
                                const float* __restrict__ anc,
                                float* __restrict__ out) {
    int t = blockIdx.x * blockDim.x + threadIdx.x;
    if (t >= TOP_K) return;
    unsigned long long key = g_keys[t];
    if (key == 0ULL) {  // pathological underflow; keep output defined
        out[t * 4 + 0] = 0.f; out[t * 4 + 1] = 0.f; out[t * 4 + 2] = 0.f; out[t * 4 + 3] = 0.f;
        out[TOP_K * 4 + t * 2 + 0] = 0.f; out[TOP_K * 4 + t * 2 + 1] = 0.f;
        g_x1[t] = 0.f; g_y1[t] = 0.f; g_x2[t] = 0.f; g_y2[t] = 0.f; g_area[t] = 0.f;
        return;
    }
    unsigned idx = 0xFFFFFFFFu - (unsigned)(key & 0xFFFFFFFFull);
    int y = idx / (W_FEAT * K_ANCH);
    int r = idx - y * (W_FEAT * K_ANCH);
    int x = r / K_ANCH;
    int k = r - x * K_ANCH;

    const float* po = obj + ((size_t)(y * W_FEAT + x)) * (2 * K_ANCH) + 2 * k;
    float p0;
    float p1 = softmax_p1(po[0], po[1], p0);

    const float* pr = reg + ((size_t)(y * W_FEAT + x)) * (4 * K_ANCH) + 4 * k;
    float r0 = pr[0], r1 = pr[1], r2 = pr[2], r3 = pr[3];
    const float* pa = anc + (size_t)idx * 4;
    float a0 = pa[0], a1 = pa[1], a2 = pa[2], a3 = pa[3];

    // unparameterize: cx = (a0 + a2/2) + r0*a2  (left-assoc, no FMA)
    float cx = __fadd_rn(__fadd_rn(a0, __fmul_rn(a2, 0.5f)), __fmul_rn(r0, a2));
    float cy = __fadd_rn(__fadd_rn(a1, __fmul_rn(a3, 0.5f)), __fmul_rn(r1, a3));
    float w  = __fmul_rn(a2, expf(r2));
    float h  = __fmul_rn(a3, expf(r3));
    float x1u = __fsub_rn(cx, __fmul_rn(w, 0.5f));
    float y1u = __fsub_rn(cy, __fmul_rn(h, 0.5f));

    // clip
    float x1 = fminf(fmaxf(x1u, 0.0f), IMG_DIM);
    float y1 = fminf(fmaxf(y1u, 0.0f), IMG_DIM);
    float x2 = fminf(fmaxf(__fadd_rn(x1u, w), 0.0f), IMG_DIM);
    float y2 = fminf(fmaxf(__fadd_rn(y1u, h), 0.0f), IMG_DIM);
    float bw = __fsub_rn(x2, x1);
    float bh = __fsub_rn(y2, y1);

    out[t * 4 + 0] = x1;
    out[t * 4 + 1] = y1;
    out[t * 4 + 2] = bw;
    out[t * 4 + 3] = bh;
    out[TOP_K * 4 + t * 2 + 0] = p0;
    out[TOP_K * 4 + t * 2 + 1] = p1;

    // NMS inputs exactly as reference recomputes them from b
    g_x1[t] = x1;
    g_y1[t] = y1;
    g_x2[t] = __fadd_rn(x1, bw);
    g_y2[t] = __fadd_rn(y1, bh);
    g_area[t] = __fmul_rn(bw, bh);
}

// ---------------- K6: NMS suppression bitmask ---------------------------------
__global__ void mask_kernel() {
    int cb = blockIdx.x, rb = blockIdx.y;
    int tid = threadIdx.x;
    __shared__ float sx1[64], sy1[64], sx2[64], sy2[64], sa[64];
    int j0 = cb * 64 + tid;
    if (j0 < TOP_K) {
        sx1[tid] = g_x1[j0]; sy1[tid] = g_y1[j0];
        sx2[tid] = g_x2[j0]; sy2[tid] = g_y2[j0];
        sa[tid]  = g_area[j0];
    }
    __syncthreads();
    int i = rb * 64 + tid;
    if (i >= TOP_K) return;
    float x1i = g_x1[i], y1i = g_y1[i], x2i = g_x2[i], y2i = g_y2[i], ai = g_area[i];
    unsigned long long bits = 0ULL;
    int jmax = min(64, TOP_K - cb * 64);
    for (int jj = 0; jj < jmax; jj++) {
        int j = cb * 64 + jj;
        if (j > i) {
            float xx1 = fmaxf(x1i, sx1[jj]);
            float yy1 = fmaxf(y1i, sy1[jj]);
            float xx2 = fminf(x2i, sx2[jj]);
            float yy2 = fminf(y2i, sy2[jj]);
            float iw = fmaxf(__fsub_rn(xx2, xx1), 0.0f);
            float ih = fmaxf(__fsub_rn(yy2, yy1), 0.0f);
            float inter = __fmul_rn(iw, ih);
            float denom = __fadd_rn(__fsub_rn(__fadd_rn(ai, sa[jj]), inter), 1e-8f);
            float iou = __fdiv_rn(inter, denom);
            if (iou > NMS_IOU_T) bits |= (1ULL << jj);
        }
    }
    g_mask[(size_t)i * COL_BLOCKS + cb] = bits;
}

// ---------------- K7: sequential greedy reduce --------------------------------
__global__ void nms_reduce_kernel(float* __restrict__ keep_out) {
    __shared__ unsigned long long removed[COL_BLOCKS];
    __shared__ int flag;
    int tid = threadIdx.x;
    if (tid < COL_BLOCKS) removed[tid] = 0ULL;
    __syncthreads();
    for (int i = 0; i < TOP_K; i++) {
        if (tid == 0) {
            int f = (int)((removed[i >> 6] >> (i & 63)) & 1ULL) ? 0 : 1;
            flag = f;
            keep_out[i] = f ? 1.0f : 0.0f;
        }
        __syncthreads();
        if (flag && tid < COL_BLOCKS)
            removed[tid] |= g_mask[(size_t)i * COL_BLOCKS + tid];
        __syncthreads();
    }
}

// ---------------- launch ------------------------------------------------------
extern "C" void kernel_launch(void* const* d_in, const int* in_sizes, int n_in,
                              void* d_out, int out_size) {
    const float* obj = (const float*)d_in[0];
    const float* reg = (const float*)d_in[1];
    const float* anc = (const float*)d_in[2];
    float* out = (float*)d_out;

    zero_kernel<<<(N_BINS + 255) / 256, 256>>>();
    score_kernel<<<(N_ANCH + 255) / 256, 256>>>(obj);
    cut_kernel<<<1, 1024>>>();
    collect_kernel<<<(N_ANCH + 255) / 256, 256>>>();
    sort_kernel<<<1, 1024>>>();
    finalize_kernel<<<(TOP_K + 255) / 256, 256>>>(obj, reg, anc, out);
    mask_kernel<<<dim3(COL_BLOCKS, COL_BLOCKS), 64>>>();
    nms_reduce_kernel<<<1, 64>>>(out + TOP_K * 4 + TOP_K * 2);
}

// round 2
// speedup vs baseline: 2.6319x; 2.6319x over previous
#include <cuda_runtime.h>
#include <cstdint>

#define H_FEAT 512
#define W_FEAT 512
#define K_ANCH 9
#define N_ANCH (H_FEAT * W_FEAT * K_ANCH)   // 2359296
#define TOP_K 4000
#define IMG_DIM 16384.0f
#define NMS_IOU_T 0.3f
#define N_BINS 131072
#define CAP 4096
#define COL_BLOCKS 63                        // ceil(4000/64) column words in use
#define ROW_WORDS 64                         // padded row stride (512B, 16B-aligned lanes)
#define MASK_ROWS 4096                       // padded row count (no bounds checks)
#define N_GROUPS 63

// ---------------- static device scratch (no allocation allowed) ----------------
__device__ float               g_scores[N_ANCH];          // 9.4 MB
__device__ unsigned int        g_hist[N_BINS];            // 512 KB
__device__ unsigned int        g_count;
__device__ unsigned int        g_cutbin;
__device__ unsigned long long  g_keys[CAP];
__device__ float               g_x1[TOP_K], g_y1[TOP_K], g_x2[TOP_K], g_y2[TOP_K], g_area[TOP_K];
// Zero-initialized at module load. Lower-triangle + padding words are NEVER
// written and therefore stay 0 across all graph replays (deterministic).
__device__ unsigned long long  g_mask[(size_t)MASK_ROWS * ROW_WORDS];   // 2 MB

// ---------------- helpers (forbid FMA contraction / fast-math drift) ----------
__device__ __forceinline__ float softmax_p1(float l0, float l1, float& p0) {
    float m  = fmaxf(l0, l1);
    float e0 = expf(__fsub_rn(l0, m));
    float e1 = expf(__fsub_rn(l1, m));
    float s  = __fadd_rn(e0, e1);
    p0 = __fdiv_rn(e0, s);
    return __fdiv_rn(e1, s);
}

// ---------------- K0: reset state (graph replays must be deterministic) -------
__global__ void zero_kernel() {
    int i = blockIdx.x * blockDim.x + threadIdx.x;
    if (i < N_BINS) g_hist[i] = 0u;
    if (i == 0) g_count = 0u;
}

// ---------------- K1: scores + histogram --------------------------------------
__global__ void score_kernel(const float* __restrict__ obj) {
    int i = blockIdx.x * blockDim.x + threadIdx.x;
    if (i >= N_ANCH) return;
    int y = i / (W_FEAT * K_ANCH);
    int r = i - y * (W_FEAT * K_ANCH);
    int x = r / K_ANCH;
    int k = r - x * K_ANCH;
    const float* p = obj + ((size_t)(y * W_FEAT + x)) * (2 * K_ANCH) + 2 * k;
    float l0 = p[0], l1 = p[1];
    float p0;
    float p1 = softmax_p1(l0, l1, p0);
    g_scores[i] = p1;
    if (p1 > 0.5f) {
        unsigned bits = __float_as_uint(p1);
        unsigned bin = (bits - 0x3F000000u) >> 6;
        if (bin > (N_BINS - 1)) bin = N_BINS - 1;
        atomicAdd(&g_hist[bin], 1u);
    }
}

// ---------------- K2: find cut bin (cumulative-from-top >= TOP_K) -------------
__global__ void cut_kernel() {
    __shared__ unsigned int csum[1024];
    int t = threadIdx.x;
    unsigned s = 0;
    #pragma unroll 4
    for (int b = 0; b < N_BINS / 1024; b++) s += g_hist[t * (N_BINS / 1024) + b];
    csum[t] = s;
    __syncthreads();
    if (t == 0) {
        unsigned running = 0;
        int cg = -1;
        for (int g = 1023; g >= 0; g--) {
            if (running + csum[g] >= (unsigned)TOP_K) { cg = g; break; }
            running += csum[g];
        }
        unsigned cut = 0;
        if (cg >= 0) {
            int base = cg * (N_BINS / 1024);
            for (int b = base + (N_BINS / 1024) - 1; b >= base; b--) {
                running += g_hist[b];
                if (running >= (unsigned)TOP_K) { cut = (unsigned)b; break; }
            }
        }
        g_cutbin = cut;
    }
}

// ---------------- K3: collect candidates above cut ----------------------------
__global__ void collect_kernel() {
    int i = blockIdx.x * blockDim.x + threadIdx.x;
    if (i >= N_ANCH) return;
    float p1 = g_scores[i];
    if (p1 > 0.5f) {
        unsigned bits = __float_as_uint(p1);
        unsigned bin = (bits - 0x3F000000u) >> 6;
        if (bin > (N_BINS - 1)) bin = N_BINS - 1;
        if (bin >= g_cutbin) {
            unsigned pos = atomicAdd(&g_count, 1u);
            if (pos < CAP) {
                g_keys[pos] = ((unsigned long long)bits << 32) |
                              (unsigned long long)(0xFFFFFFFFu - (unsigned)i);
            }
        }
    }
}

// ---------------- K4: one-block bitonic sort (descending), n = 4096 -----------
__global__ void sort_kernel() {
    __shared__ unsigned long long s[CAP];
    unsigned cnt = g_count;
    if (cnt > CAP) cnt = CAP;
    for (int i = threadIdx.x; i < CAP; i += blockDim.x)
        s[i] = (i < (int)cnt) ? g_keys[i] : 0ULL;
    __syncthreads();
    for (int k = 2; k <= CAP; k <<= 1) {
        for (int j = k >> 1; j > 0; j >>= 1) {
            for (int i = threadIdx.x; i < CAP; i += blockDim.x) {
                int ixj = i ^ j;
                if (ixj > i) {
                    unsigned long long a = s[i], b = s[ixj];
                    bool up = ((i & k) == 0);
                    if (up ? (a < b) : (a > b)) { s[i] = b; s[ixj] = a; }
                }
            }
            __syncthreads();
        }
    }
    for (int i = threadIdx.x; i < CAP; i += blockDim.x) g_keys[i] = s[i];
}

// ---------------- K5: decode boxes, write b & o, prep NMS inputs --------------
__global__ void finalize_kernel(const float* __restrict__ obj,
                                const float* __restrict__ reg,
                                const float* __restrict__ anc,
                                float* __restrict__ out) {
    int t = blockIdx.x * blockDim.x + threadIdx.x;
    if (t >= TOP_K) return;
    unsigned long long key = g_keys[t];
    if (key == 0ULL) {  // pathological underflow; keep output defined
        out[t * 4 + 0] = 0.f; out[t * 4 + 1] = 0.f; out[t * 4 + 2] = 0.f; out[t * 4 + 3] = 0.f;
        out[TOP_K * 4 + t * 2 + 0] = 0.f; out[TOP_K * 4 + t * 2 + 1] = 0.f;
        g_x1[t] = 0.f; g_y1[t] = 0.f; g_x2[t] = 0.f; g_y2[t] = 0.f; g_area[t] = 0.f;
        return;
    }
    unsigned idx = 0xFFFFFFFFu - (unsigned)(key & 0xFFFFFFFFull);
    int y = idx / (W_FEAT * K_ANCH);
    int r = idx - y * (W_FEAT * K_ANCH);
    int x = r / K_ANCH;
    int k = r - x * K_ANCH;

    const float* po = obj + ((size_t)(y * W_FEAT + x)) * (2 * K_ANCH) + 2 * k;
    float p0;
    float p1 = softmax_p1(po[0], po[1], p0);

    const float* pr = reg + ((size_t)(y * W_FEAT + x)) * (4 * K_ANCH) + 4 * k;
    float r0 = pr[0], r1 = pr[1], r2 = pr[2], r3 = pr[3];
    const float* pa = anc + (size_t)idx * 4;
    float a0 = pa[0], a1 = pa[1], a2 = pa[2], a3 = pa[3];

    float cx = __fadd_rn(__fadd_rn(a0, __fmul_rn(a2, 0.5f)), __fmul_rn(r0, a2));
    float cy = __fadd_rn(__fadd_rn(a1, __fmul_rn(a3, 0.5f)), __fmul_rn(r1, a3));
    float w  = __fmul_rn(a2, expf(r2));
    float h  = __fmul_rn(a3, expf(r3));
    float x1u = __fsub_rn(cx, __fmul_rn(w, 0.5f));
    float y1u = __fsub_rn(cy, __fmul_rn(h, 0.5f));

    float x1 = fminf(fmaxf(x1u, 0.0f), IMG_DIM);
    float y1 = fminf(fmaxf(y1u, 0.0f), IMG_DIM);
    float x2 = fminf(fmaxf(__fadd_rn(x1u, w), 0.0f), IMG_DIM);
    float y2 = fminf(fmaxf(__fadd_rn(y1u, h), 0.0f), IMG_DIM);
    float bw = __fsub_rn(x2, x1);
    float bh = __fsub_rn(y2, y1);

    out[t * 4 + 0] = x1;
    out[t * 4 + 1] = y1;
    out[t * 4 + 2] = bw;
    out[t * 4 + 3] = bh;
    out[TOP_K * 4 + t * 2 + 0] = p0;
    out[TOP_K * 4 + t * 2 + 1] = p1;

    g_x1[t] = x1;
    g_y1[t] = y1;
    g_x2[t] = __fadd_rn(x1, bw);
    g_y2[t] = __fadd_rn(y1, bh);
    g_area[t] = __fmul_rn(bw, bh);
}

// ---------------- K6: NMS suppression bitmask (upper triangle only) -----------
__global__ void mask_kernel() {
    int cb = blockIdx.x, rb = blockIdx.y;
    if (cb < rb) return;   // lower-triangle words stay 0 (never written)
    int tid = threadIdx.x;
    __shared__ float sx1[64], sy1[64], sx2[64], sy2[64], sa[64];
    int j0 = cb * 64 + tid;
    if (j0 < TOP_K) {
        sx1[tid] = g_x1[j0]; sy1[tid] = g_y1[j0];
        sx2[tid] = g_x2[j0]; sy2[tid] = g_y2[j0];
        sa[tid]  = g_area[j0];
    }
    __syncthreads();
    int i = rb * 64 + tid;
    if (i >= TOP_K) return;
    float x1i = g_x1[i], y1i = g_y1[i], x2i = g_x2[i], y2i = g_y2[i], ai = g_area[i];
    unsigned long long bits = 0ULL;
    int jmax = min(64, TOP_K - cb * 64);
    for (int jj = 0; jj < jmax; jj++) {
        int j = cb * 64 + jj;
        if (j > i) {
            float xx1 = fmaxf(x1i, sx1[jj]);
            float yy1 = fmaxf(y1i, sy1[jj]);
            float xx2 = fminf(x2i, sx2[jj]);
            float yy2 = fminf(y2i, sy2[jj]);
            float iw = fmaxf(__fsub_rn(xx2, xx1), 0.0f);
            float ih = fmaxf(__fsub_rn(yy2, yy1), 0.0f);
            float inter = __fmul_rn(iw, ih);
            float denom = __fadd_rn(__fsub_rn(__fadd_rn(ai, sa[jj]), inter), 1e-8f);
            float iou = __fdiv_rn(inter, denom);
            if (iou > NMS_IOU_T) bits |= (1ULL << jj);
        }
    }
    g_mask[(size_t)i * ROW_WORDS + cb] = bits;
}

// ---------------- K7: blocked greedy reduce, single warp ----------------------
// Lane l owns removed-words 2l and 2l+1 (acc0, acc1). Lane 0 runs the 64-row
// serial inner loop per group on a register-resident 64x64 diagonal block,
// prefetched one group ahead. Boundary: all lanes OR kept rows' mask words.
__global__ void __launch_bounds__(32) nms_reduce_kernel(float* __restrict__ keep_out) {
    const int lane = threadIdx.x;
    unsigned long long acc0 = 0ULL, acc1 = 0ULL;
    unsigned long long diag[64];

    // Prefetch diagonal block of group 0 (rows 0..63, word 0) into lane 0 regs.
    if (lane == 0) {
        #pragma unroll
        for (int jj = 0; jj < 64; jj++)
            diag[jj] = g_mask[(size_t)jj * ROW_WORDS + 0];
    }

    for (int g = 0; g < N_GROUPS; g++) {
        const int r0 = g * 64;

        // Fetch current removed-word for this group from its owner lane.
        unsigned long long wsel = (g & 1) ? acc1 : acc0;
        unsigned long long word = __shfl_sync(0xffffffffu, wsel, g >> 1);

        // Serial greedy inner loop (lane 0, all registers).
        unsigned long long keepm = 0ULL;
        if (lane == 0) {
            #pragma unroll
            for (int jj = 0; jj < 64; jj++) {
                unsigned long long bit = (word >> jj) & 1ULL;   // 1 = removed
                unsigned long long m = bit - 1ULL;              // keep -> all ones
                word |= diag[jj] & m;
                keepm |= (bit ^ 1ULL) << jj;
            }
        }
        keepm = __shfl_sync(0xffffffffu, keepm, 0);

        // Write keep outputs (2 per lane). Padding rows (>=TOP_K) skipped.
        int r = r0 + 2 * lane;
        if (r < TOP_K)     keep_out[r]     = (float)((keepm >> (2 * lane)) & 1ULL);
        if (r + 1 < TOP_K) keep_out[r + 1] = (float)((keepm >> (2 * lane + 1)) & 1ULL);

        // Prefetch next group's diagonal (padding rows read zeros).
        if (lane == 0 && g + 1 < N_GROUPS) {
            const int r0n = (g + 1) * 64;
            #pragma unroll
            for (int jj = 0; jj < 64; jj++)
                diag[jj] = g_mask[(size_t)(r0n + jj) * ROW_WORDS + (g + 1)];
        }

        // Boundary: OR kept rows' full mask rows into distributed acc.
        const unsigned long long* base = g_mask + (size_t)r0 * ROW_WORDS + 2 * lane;
        #pragma unroll
        for (int jj = 0; jj < 64; jj++) {
            unsigned long long m = 0ULL - ((keepm >> jj) & 1ULL);  // kept -> ones
            ulonglong2 v = *reinterpret_cast<const ulonglong2*>(base + (size_t)jj * ROW_WORDS);
            acc0 |= v.x & m;
            acc1 |= v.y & m;
        }
    }
}

// ---------------- launch ------------------------------------------------------
extern "C" void kernel_launch(void* const* d_in, const int* in_sizes, int n_in,
                              void* d_out, int out_size) {
    const float* obj = (const float*)d_in[0];
    const float* reg = (const float*)d_in[1];
    const float* anc = (const float*)d_in[2];
    float* out = (float*)d_out;

    zero_kernel<<<(N_BINS + 255) / 256, 256>>>();
    score_kernel<<<(N_ANCH + 255) / 256, 256>>>(obj);
    cut_kernel<<<1, 1024>>>();
    collect_kernel<<<(N_ANCH + 255) / 256, 256>>>();
    sort_kernel<<<1, 1024>>>();
    finalize_kernel<<<(TOP_K + 255) / 256, 256>>>(obj, reg, anc, out);
    mask_kernel<<<dim3(COL_BLOCKS, COL_BLOCKS), 64>>>();
    nms_reduce_kernel<<<1, 32>>>(out + TOP_K * 4 + TOP_K * 2);
}